// round 1
// baseline (speedup 1.0000x reference)
#include <cuda_runtime.h>
#include <math.h>

// ---------------- problem constants ----------------
#define HH      1024
#define WWIDTH  1024
#define NPIX    (HH * WWIDTH)
#define KK      8
#define CC      3
#define WS      11
#define RAD     5

// ---------------- tiling ----------------
#define TW       32
#define TH       32
#define HTW      (TW + 2 * RAD)   // 42
#define HTH      (TH + 2 * RAD)   // 42
#define HT       (HTW * HTH)      // 1764
#define NTHREADS 256
#define PPT      4                // pixels per thread = TH / (NTHREADS/TW)
#define PRE_BLOCKS  2048
#define MAIN_BLOCKS (WWIDTH / TW * HH / TH)  // 1024

// ---------------- scratch (static device globals; no allocation) ----------------
__device__ float g_lY_part[KK * PRE_BLOCKS];
__device__ float g_lG[KK];
__device__ float g_q_part[MAIN_BLOCKS];

// gaussian(ws, ws/6), normalized — matches reference window (f32-rounded)
__device__ __forceinline__ void compute_gw(float* gw) {
    const float sg = (float)WS / 6.0f;
    float t[WS];
    float s = 0.f;
#pragma unroll
    for (int i = 0; i < WS; i++) {
        float d = (float)(i - RAD);
        t[i] = expf(-(d * d) / (2.0f * sg * sg));
        s += t[i];
    }
    float inv = 1.0f / s;
#pragma unroll
    for (int i = 0; i < WS; i++) gw[i] = t[i] * inv;
}

// ---------------- pass 1: lY[k] = mean over pixels of blur(mean_c bunch[k]) ----------------
// mean(blur(s)) = (1/HW) * sum_q s[q] * Wx(x) * Wy(y)   (zero-padded blur => truncated
// edge weights), so no muY field needs to be materialized.
__global__ __launch_bounds__(NTHREADS) void lY_prepass(const float* __restrict__ bunch) {
    float gw[WS];
    compute_gw(gw);
    int tid = threadIdx.x;
    float acc[KK];
#pragma unroll
    for (int k = 0; k < KK; k++) acc[k] = 0.f;

    for (int p = blockIdx.x * NTHREADS + tid; p < NPIX; p += PRE_BLOCKS * NTHREADS) {
        int y = p >> 10;
        int x = p & (WWIDTH - 1);
        float wx = 0.f, wy = 0.f;
#pragma unroll
        for (int j = 0; j < WS; j++) {
            int d = j - RAD;
            if ((unsigned)(x - d) < WWIDTH) wx += gw[j];
            if ((unsigned)(y - d) < HH)     wy += gw[j];
        }
        float w = wx * wy * (1.f / 3.f);
#pragma unroll
        for (int k = 0; k < KK; k++) {
            float s = bunch[(size_t)(k * 3 + 0) * NPIX + p]
                    + bunch[(size_t)(k * 3 + 1) * NPIX + p]
                    + bunch[(size_t)(k * 3 + 2) * NPIX + p];
            acc[k] += w * s;
        }
    }

    __shared__ float red[NTHREADS];
#pragma unroll
    for (int k = 0; k < KK; k++) {
        red[tid] = acc[k];
        __syncthreads();
        for (int off = NTHREADS / 2; off > 0; off >>= 1) {
            if (tid < off) red[tid] += red[tid + off];
            __syncthreads();
        }
        if (tid == 0) g_lY_part[k * PRE_BLOCKS + blockIdx.x] = red[0];
        __syncthreads();
    }
}

__global__ __launch_bounds__(NTHREADS) void reduce_lY() {
    __shared__ double red[NTHREADS];
    int tid = threadIdx.x;
    for (int k = 0; k < KK; k++) {
        double s = 0.0;
        for (int i = tid; i < PRE_BLOCKS; i += NTHREADS)
            s += (double)g_lY_part[k * PRE_BLOCKS + i];
        red[tid] = s;
        __syncthreads();
        for (int off = NTHREADS / 2; off > 0; off >>= 1) {
            if (tid < off) red[tid] += red[tid + off];
            __syncthreads();
        }
        if (tid == 0) {
            double lY = red[0] / (double)NPIX;
            double d = lY - 0.5;
            g_lG[k] = (float)exp(-(d * d) / 0.08);  // DENOM_G = 2*0.2^2
        }
        __syncthreads();
    }
}

// ---------------- main fused pass ----------------
__device__ __forceinline__ void hblur(const float* __restrict__ f,
                                      float* __restrict__ hb,
                                      const float* gw, int tid) {
    for (int m = tid; m < HTH * TW; m += NTHREADS) {
        int hr = m >> 5;          // TW == 32
        int c  = m & 31;
        const float* row = f + hr * HTW + c;
        float s = 0.f;
#pragma unroll
        for (int j = 0; j < WS; j++) s += gw[j] * row[j];
        hb[m] = s;
    }
}

__device__ __forceinline__ float vblur(const float* __restrict__ hb,
                                       const float* gw, int r, int tx) {
    float s = 0.f;
#pragma unroll
    for (int j = 0; j < WS; j++) s += gw[j] * hb[(r + j) * TW + tx];
    return s;
}

__global__ __launch_bounds__(NTHREADS) void mef_main(
    const float* __restrict__ img,     // [3, H, W]
    const float* __restrict__ bunch,   // [K, 3, H, W]
    float* __restrict__ patch_out)     // [H, W] (may be null)
{
    __shared__ float s_oc0[HT], s_oc1[HT], s_oc2[HT];
    __shared__ float s_f0[HT], s_f1[HT], s_f2[HT];
    __shared__ float s_hb[HTH * TW];

    float gw[WS];
    compute_gw(gw);

    int tid = threadIdx.x;
    int tx = tid & 31, ty = tid >> 5;
    int bx = blockIdx.x, by = blockIdx.y;
    int gx0 = bx * TW - RAD, gy0 = by * TH - RAD;

    // load output channels (with halo); build s_o, s_o^2 fields
    for (int e = tid; e < HT; e += NTHREADS) {
        int hy = e / HTW, hx = e - hy * HTW;
        int gy = gy0 + hy, gx = gx0 + hx;
        bool in = ((unsigned)gy < HH) && ((unsigned)gx < WWIDTH);
        int off = gy * WWIDTH + gx;
        float o0 = in ? img[0 * NPIX + off] : 0.f;
        float o1 = in ? img[1 * NPIX + off] : 0.f;
        float o2 = in ? img[2 * NPIX + off] : 0.f;
        s_oc0[e] = o0; s_oc1[e] = o1; s_oc2[e] = o2;
        s_f0[e] = (o0 + o1 + o2) * (1.f / 3.f);
        s_f1[e] = (o0 * o0 + o1 * o1 + o2 * o2) * (1.f / 3.f);
    }
    __syncthreads();

    float muX[PPT], sX2[PPT];
    hblur(s_f0, s_hb, gw, tid);
    __syncthreads();
#pragma unroll
    for (int i = 0; i < PPT; i++) muX[i] = vblur(s_hb, gw, ty + 8 * i, tx);
    __syncthreads();
    hblur(s_f1, s_hb, gw, tid);
    __syncthreads();
#pragma unroll
    for (int i = 0; i < PPT; i++) {
        float m2 = vblur(s_hb, gw, ty + 8 * i, tx);
        sX2[i] = m2 - muX[i] * muX[i];
    }
    __syncthreads();

    float best[PPT], bestXY[PPT], num[PPT], den[PPT];
    int idx[PPT];
#pragma unroll
    for (int i = 0; i < PPT; i++) {
        best[i] = -1e30f; bestXY[i] = 0.f; num[i] = 0.f; den[i] = 0.f; idx[i] = 0;
    }

    for (int k = 0; k < KK; k++) {
        const float* b0 = bunch + (size_t)(k * 3 + 0) * NPIX;
        const float* b1 = bunch + (size_t)(k * 3 + 1) * NPIX;
        const float* b2 = bunch + (size_t)(k * 3 + 2) * NPIX;
        for (int e = tid; e < HT; e += NTHREADS) {
            int hy = e / HTW, hx = e - hy * HTW;
            int gy = gy0 + hy, gx = gx0 + hx;
            bool in = ((unsigned)gy < HH) && ((unsigned)gx < WWIDTH);
            int off = gy * WWIDTH + gx;
            float v0 = in ? b0[off] : 0.f;
            float v1 = in ? b1[off] : 0.f;
            float v2 = in ? b2[off] : 0.f;
            s_f0[e] = (v0 + v1 + v2) * (1.f / 3.f);
            s_f1[e] = (v0 * v0 + v1 * v1 + v2 * v2) * (1.f / 3.f);
            s_f2[e] = (v0 * s_oc0[e] + v1 * s_oc1[e] + v2 * s_oc2[e]) * (1.f / 3.f);
        }
        __syncthreads();

        float muY[PPT], sY2[PPT], sXY[PPT];
        hblur(s_f0, s_hb, gw, tid);
        __syncthreads();
#pragma unroll
        for (int i = 0; i < PPT; i++) muY[i] = vblur(s_hb, gw, ty + 8 * i, tx);
        __syncthreads();
        hblur(s_f1, s_hb, gw, tid);
        __syncthreads();
#pragma unroll
        for (int i = 0; i < PPT; i++) {
            float m2 = vblur(s_hb, gw, ty + 8 * i, tx);
            sY2[i] = m2 - muY[i] * muY[i];
        }
        __syncthreads();
        hblur(s_f2, s_hb, gw, tid);
        __syncthreads();
#pragma unroll
        for (int i = 0; i < PPT; i++) {
            float mxy = vblur(s_hb, gw, ty + 8 * i, tx);
            sXY[i] = mxy - muX[i] * muY[i];
        }
        __syncthreads();

        float lGk = g_lG[k];
#pragma unroll
        for (int i = 0; i < PPT; i++) {
            if (sY2[i] > best[i]) { best[i] = sY2[i]; bestXY[i] = sXY[i]; idx[i] = k; }
            float dm = muY[i] - 0.5f;
            float w = lGk * __expf(-(dm * dm) * (1.0f / 0.08f));  // DENOM_L = 0.08
            num[i] += w * muY[i];
            den[i] += w;
        }
    }

    // epilogue: l_map, cs_map, q partial, patch_index
    float qsum = 0.f;
#pragma unroll
    for (int i = 0; i < PPT; i++) {
        float muYb = num[i] / den[i];
        float l  = (2.f * muX[i] * muYb + 1e-4f) /
                   fmaxf(muX[i] * muX[i] + muYb * muYb + 1e-4f, 1e-6f);   // C1 = 0.01^2
        float cs = (2.f * bestXY[i] + 9e-4f) /
                   fmaxf(sX2[i] + best[i] + 9e-4f, 1e-6f);                 // C2 = 0.03^2
        qsum += l * cs;
        if (patch_out) {
            int r = ty + 8 * i;
            int gy = by * TH + r, gx = bx * TW + tx;
            patch_out[gy * WWIDTH + gx] = (float)idx[i];
        }
    }

    __syncthreads();
    s_hb[tid] = qsum;
    __syncthreads();
    for (int off = NTHREADS / 2; off > 0; off >>= 1) {
        if (tid < off) s_hb[tid] += s_hb[tid + off];
        __syncthreads();
    }
    if (tid == 0) g_q_part[by * gridDim.x + bx] = s_hb[0];
}

__global__ __launch_bounds__(NTHREADS) void reduce_q(float* __restrict__ q_out) {
    __shared__ double red[NTHREADS];
    int tid = threadIdx.x;
    double s = 0.0;
    for (int i = tid; i < MAIN_BLOCKS; i += NTHREADS) s += (double)g_q_part[i];
    red[tid] = s;
    __syncthreads();
    for (int off = NTHREADS / 2; off > 0; off >>= 1) {
        if (tid < off) red[tid] += red[tid + off];
        __syncthreads();
    }
    if (tid == 0) q_out[0] = (float)(red[0] / (double)NPIX);
}

// ---------------- launch ----------------
extern "C" void kernel_launch(void* const* d_in, const int* in_sizes, int n_in,
                              void* d_out, int out_size) {
    // identify inputs (output: 3*NPIX, bunch: 24*NPIX) defensively by size
    const float* a = (const float*)d_in[0];
    const float* b = (const float*)d_in[1];
    const float* img;
    const float* bunch;
    if (in_sizes[0] > in_sizes[1]) { bunch = a; img = b; }
    else                           { img = a;  bunch = b; }

    float* out = (float*)d_out;
    float* qdst = nullptr;
    float* patch = nullptr;
    if (out_size >= NPIX + 1)      { qdst = out; patch = out + 1; }
    else if (out_size == NPIX)     { patch = out; }
    else                           { qdst = out; }

    lY_prepass<<<PRE_BLOCKS, NTHREADS>>>(bunch);
    reduce_lY<<<1, NTHREADS>>>();
    mef_main<<<dim3(WWIDTH / TW, HH / TH), NTHREADS>>>(img, bunch, patch);
    if (qdst) reduce_q<<<1, NTHREADS>>>(qdst);
}

// round 3
// speedup vs baseline: 1.2764x; 1.2764x over previous
#include <cuda_runtime.h>
#include <math.h>

// ---------------- problem constants ----------------
#define HH      1024
#define WW      1024
#define NPIX    (HH * WW)
#define KK      8
#define WS      11
#define RAD     5

// ---------------- tiling ----------------
#define TW       32
#define TH       32
#define HTW      42            // TW + 2*RAD
#define HTH      42
#define HT       (HTW * HTH)   // 1764
#define NT       256
#define NLOAD    7             // ceil(HT / NT)
#define VBS      43            // vb row stride in float4
#define PREB     1024
#define MAINB    1024          // (WW/TW)*(HH/TH)

// smem layout (bytes)
#define OFF_PACK 0
#define OFF_VB   28224                   // HT * 16
#define OFF_OC   (28224 + 22016)         // + 32*43*16
#define SMEM_TOTAL (OFF_OC + 3 * HT * 4) // 71408

struct GW { float w[WS]; };

// ---------------- scratch (static device globals; no allocation) ----------------
__device__ float g_lY_part[KK * PREB];
__device__ float g_lG[KK];
__device__ float g_q_part[MAINB];
__device__ int   g_done_pre  = 0;
__device__ int   g_done_main = 0;

// ======================= pass 1: lY / lG =======================
// mean(blur(s)) = (1/HW) * sum_p s[p] * Wx(x) * Wy(y)  (zero-padded conv =>
// truncated edge weights). Last block folds the reduction and computes lG[k].
__global__ __launch_bounds__(NT) void lY_prepass(const float* __restrict__ bunch, GW gwp) {
    const float* gw = gwp.w;
    int tid = threadIdx.x;
    int idx = blockIdx.x * NT + tid;          // float4 index; PREB*NT == NPIX/4
    int y  = idx >> 8;
    int x0 = (idx & 255) << 2;

    float wy = 0.f;
#pragma unroll
    for (int j = 0; j < WS; j++) { int d = j - RAD; if ((unsigned)(y - d) < HH) wy += gw[j]; }
    float w[4];
#pragma unroll
    for (int e = 0; e < 4; e++) {
        int x = x0 + e;
        float wx = 0.f;
#pragma unroll
        for (int j = 0; j < WS; j++) { int d = j - RAD; if ((unsigned)(x - d) < WW) wx += gw[j]; }
        w[e] = wx * wy * (1.f / 3.f);
    }

    float acc[KK];
    const float4* b4 = (const float4*)bunch;
#pragma unroll
    for (int k = 0; k < KK; k++) {
        float4 a = b4[(size_t)(k * 3 + 0) * (NPIX / 4) + idx];
        float4 b = b4[(size_t)(k * 3 + 1) * (NPIX / 4) + idx];
        float4 c = b4[(size_t)(k * 3 + 2) * (NPIX / 4) + idx];
        acc[k] = w[0] * (a.x + b.x + c.x) + w[1] * (a.y + b.y + c.y)
               + w[2] * (a.z + b.z + c.z) + w[3] * (a.w + b.w + c.w);
    }

    __shared__ float red[NT];
#pragma unroll
    for (int k = 0; k < KK; k++) {
        red[tid] = acc[k];
        __syncthreads();
        for (int o = NT / 2; o > 0; o >>= 1) { if (tid < o) red[tid] += red[tid + o]; __syncthreads(); }
        if (tid == 0) g_lY_part[k * PREB + blockIdx.x] = red[0];
        __syncthreads();
    }

    __shared__ int isLast;
    if (tid == 0) {
        __threadfence();
        isLast = (atomicAdd(&g_done_pre, 1) == PREB - 1);
    }
    __syncthreads();
    if (isLast) {
        __threadfence();
        for (int k = 0; k < KK; k++) {
            float s = 0.f;
            for (int i = tid; i < PREB; i += NT) s += g_lY_part[k * PREB + i];
            red[tid] = s;
            __syncthreads();
            for (int o = NT / 2; o > 0; o >>= 1) { if (tid < o) red[tid] += red[tid + o]; __syncthreads(); }
            if (tid == 0) {
                double lY = (double)red[0] / (double)NPIX;
                double d = lY - 0.5;
                g_lG[k] = (float)exp(-(d * d) / 0.08);   // DENOM_G = 2*0.2^2
            }
            __syncthreads();
        }
        if (tid == 0) g_done_pre = 0;  // self-reset for next graph replay
    }
}

// ======================= separable blur helpers =======================
// Vertical first, 4 consecutive output rows per task => 14 loads per 4 outputs.
__device__ __forceinline__ void vpass(const float4* __restrict__ sp, float4* __restrict__ vb,
                                      const float* gw, int tid) {
    for (int t = tid; t < 336; t += NT) {          // 8 rowgroups * 42 cols
        int rg = t / 42, c = t - rg * 42;
        int r0 = rg * 4;
        float ox[4], oy[4], oz[4];
#pragma unroll
        for (int i = 0; i < 4; i++) { ox[i] = 0.f; oy[i] = 0.f; oz[i] = 0.f; }
        const float4* p = sp + r0 * HTW + c;
#pragma unroll
        for (int j = 0; j < 14; j++) {
            float4 v = p[j * HTW];
#pragma unroll
            for (int i = 0; i < 4; i++) {
                if (i <= j && j - i <= 10) {
                    float g = gw[j - i];
                    ox[i] += g * v.x; oy[i] += g * v.y; oz[i] += g * v.z;
                }
            }
        }
#pragma unroll
        for (int i = 0; i < 4; i++) vb[(r0 + i) * VBS + c] = make_float4(ox[i], oy[i], oz[i], 0.f);
    }
}

// Horizontal: warp = 4-col segment, lane = row. Row stride 43 float4.
__device__ __forceinline__ void hpass(const float4* __restrict__ vb, const float* gw,
                                      int row, int x0, float3* out) {
    float ox[4], oy[4], oz[4];
#pragma unroll
    for (int i = 0; i < 4; i++) { ox[i] = 0.f; oy[i] = 0.f; oz[i] = 0.f; }
    const float4* p = vb + row * VBS + x0;
#pragma unroll
    for (int j = 0; j < 14; j++) {
        float4 v = p[j];
#pragma unroll
        for (int i = 0; i < 4; i++) {
            if (i <= j && j - i <= 10) {
                float g = gw[j - i];
                ox[i] += g * v.x; oy[i] += g * v.y; oz[i] += g * v.z;
            }
        }
    }
#pragma unroll
    for (int i = 0; i < 4; i++) out[i] = make_float3(ox[i], oy[i], oz[i]);
}

// ======================= main fused pass =======================
// Works in SHIFTED domain v' = v - 0.5 (exact identities, since sum(w)=1 and the
// reference zero-pads raw values => padded v' = -0.5):
//   sigma²  = blur(mean_c v'²) - blur(mean_c v')²
//   sigmaXY = blur(mean_c x'y') - mu'x mu'y
//   mu      = mu' + 0.5
// This shrinks blur magnitudes ~4x and the cancellation term ~350x, cutting the
// absolute error of sigma² ~10x -> argmax(patch_index) matches the reference's
// own rounding floor.
__global__ __launch_bounds__(NT) void mef_main_k(
    const float* __restrict__ img,
    const float* __restrict__ bunch,
    float* __restrict__ patch_out,
    float* __restrict__ q_out,
    GW gwp)
{
    extern __shared__ char sm[];
    float4* s_pack = (float4*)(sm + OFF_PACK);
    float4* s_vb   = (float4*)(sm + OFF_VB);
    float*  s_oc0  = (float*)(sm + OFF_OC);
    float*  s_oc1  = s_oc0 + HT;
    float*  s_oc2  = s_oc1 + HT;
    const float* gw = gwp.w;

    int tid = threadIdx.x;
    int tx = tid & 31, ty = tid >> 5;
    int bx = blockIdx.x, by = blockIdx.y;
    int gx0 = bx * TW - RAD, gy0 = by * TH - RAD;

    int goff[NLOAD];
#pragma unroll
    for (int i = 0; i < NLOAD; i++) {
        int e = tid + i * NT;
        if (e < HT) {
            int hy = e / HTW, hx = e - hy * HTW;
            int gy = gy0 + hy, gx = gx0 + hx;
            goff[i] = (((unsigned)gy < HH) && ((unsigned)gx < WW)) ? gy * WW + gx : -1;
        } else goff[i] = -2;
    }

    // ---- X pass: load output channels (shifted), build (s'x, s'x²) ----
#pragma unroll
    for (int i = 0; i < NLOAD; i++) {
        int e = tid + i * NT;
        if (e < HT) {
            float o0 = -0.5f, o1 = -0.5f, o2 = -0.5f;
            int o = goff[i];
            if (o >= 0) {
                o0 = img[o] - 0.5f; o1 = img[NPIX + o] - 0.5f; o2 = img[2 * NPIX + o] - 0.5f;
            }
            s_oc0[e] = o0; s_oc1[e] = o1; s_oc2[e] = o2;
            s_pack[e] = make_float4((o0 + o1 + o2) * (1.f / 3.f),
                                    (o0 * o0 + o1 * o1 + o2 * o2) * (1.f / 3.f), 0.f, 0.f);
        }
    }
    __syncthreads();

    int row = tx;           // thread's pixel row within tile
    int x0c = ty * 4;       // thread's 4 consecutive pixel cols

    vpass(s_pack, s_vb, gw, tid);
    __syncthreads();
    float3 xo[4];
    hpass(s_vb, gw, row, x0c, xo);
    float muXs[4], sX2[4];   // muXs = shifted mean
#pragma unroll
    for (int i = 0; i < 4; i++) { muXs[i] = xo[i].x; sX2[i] = xo[i].y - muXs[i] * muXs[i]; }
    __syncthreads();

    float best[4], bestXY[4], num[4], den[4];
    int pidx[4];
#pragma unroll
    for (int i = 0; i < 4; i++) {
        best[i] = -1e30f; bestXY[i] = 0.f; num[i] = 0.f; den[i] = 0.f; pidx[i] = 0;
    }

    for (int k = 0; k < KK; k++) {
        const float* b0 = bunch + (size_t)(3 * k + 0) * NPIX;
        const float* b1 = bunch + (size_t)(3 * k + 1) * NPIX;
        const float* b2 = bunch + (size_t)(3 * k + 2) * NPIX;
#pragma unroll
        for (int i = 0; i < NLOAD; i++) {
            int e = tid + i * NT;
            if (e < HT) {
                float v0 = -0.5f, v1 = -0.5f, v2 = -0.5f;
                int o = goff[i];
                if (o >= 0) { v0 = b0[o] - 0.5f; v1 = b1[o] - 0.5f; v2 = b2[o] - 0.5f; }
                s_pack[e] = make_float4(
                    (v0 + v1 + v2) * (1.f / 3.f),
                    (v0 * v0 + v1 * v1 + v2 * v2) * (1.f / 3.f),
                    (v0 * s_oc0[e] + v1 * s_oc1[e] + v2 * s_oc2[e]) * (1.f / 3.f), 0.f);
            }
        }
        __syncthreads();
        vpass(s_pack, s_vb, gw, tid);
        __syncthreads();
        float3 yo[4];
        hpass(s_vb, gw, row, x0c, yo);

        float lGk = g_lG[k];
#pragma unroll
        for (int i = 0; i < 4; i++) {
            float muYs = yo[i].x;                       // shifted mean
            float sY2 = yo[i].y - muYs * muYs;
            float sXY = yo[i].z - muXs[i] * muYs;
            if (sY2 > best[i]) { best[i] = sY2; bestXY[i] = sXY; pidx[i] = k; }
            float muY = muYs + 0.5f;
            float dm = muY - 0.5f;                       // == muYs
            float wgt = lGk * __expf(-(dm * dm) * (1.f / 0.08f));  // DENOM_L = 0.08
            num[i] += wgt * muY;
            den[i] += wgt;
        }
        __syncthreads();   // protect s_pack / s_vb for next k
    }

    // ---- epilogue ----
    float qsum = 0.f;
    float* sidx = (float*)s_vb;   // reuse: 1024 floats
#pragma unroll
    for (int i = 0; i < 4; i++) {
        float muX  = muXs[i] + 0.5f;
        float muYb = num[i] / den[i];
        float l  = (2.f * muX * muYb + 1e-4f) /
                   fmaxf(muX * muX + muYb * muYb + 1e-4f, 1e-6f);      // C1 = 0.01^2
        float cs = (2.f * bestXY[i] + 9e-4f) /
                   fmaxf(sX2[i] + best[i] + 9e-4f, 1e-6f);              // C2 = 0.03^2
        qsum += l * cs;
        sidx[row * 32 + x0c + i] = (float)pidx[i];
    }
    __syncthreads();
    if (patch_out) {
#pragma unroll
        for (int i = 0; i < 4; i++) {
            int rr = ty + 8 * i;
            patch_out[(by * TH + rr) * WW + bx * TW + tx] = sidx[rr * 32 + tx];
        }
    }

    // ---- deterministic q reduction: block tree + last-block fold ----
    float* qred = (float*)s_pack;
    qred[tid] = qsum;
    __syncthreads();
    for (int o = NT / 2; o > 0; o >>= 1) { if (tid < o) qred[tid] += qred[tid + o]; __syncthreads(); }
    if (tid == 0) g_q_part[by * gridDim.x + bx] = qred[0];

    __shared__ int isLast;
    if (tid == 0) {
        __threadfence();
        isLast = (atomicAdd(&g_done_main, 1) == MAINB - 1);
    }
    __syncthreads();
    if (isLast) {
        __threadfence();
        float s = 0.f;
        for (int i = tid; i < MAINB; i += NT) s += g_q_part[i];
        qred[tid] = s;
        __syncthreads();
        for (int o = NT / 2; o > 0; o >>= 1) { if (tid < o) qred[tid] += qred[tid + o]; __syncthreads(); }
        if (tid == 0) {
            if (q_out) q_out[0] = qred[0] / (float)NPIX;
            g_done_main = 0;
        }
    }
}

// ---------------- launch ----------------
extern "C" void kernel_launch(void* const* d_in, const int* in_sizes, int n_in,
                              void* d_out, int out_size) {
    const float* a = (const float*)d_in[0];
    const float* b = (const float*)d_in[1];
    const float* img;
    const float* bunch;
    if (in_sizes[0] > in_sizes[1]) { bunch = a; img = b; }
    else                           { img = a;  bunch = b; }

    float* out = (float*)d_out;
    float* qdst = nullptr;
    float* patch = nullptr;
    if (out_size >= NPIX + 1)      { qdst = out; patch = out + 1; }
    else if (out_size == NPIX)     { patch = out; }
    else                           { qdst = out; }

    // host-side double-precision gaussian window (matches numpy's f64 window)
    GW gwp;
    {
        double t[WS], s = 0.0;
        double sg = (double)WS / 6.0;
        for (int i = 0; i < WS; i++) {
            double d = (double)(i - RAD);
            t[i] = exp(-(d * d) / (2.0 * sg * sg));
            s += t[i];
        }
        for (int i = 0; i < WS; i++) gwp.w[i] = (float)(t[i] / s);
    }

    static bool attr_set = false;
    if (!attr_set) {
        cudaFuncSetAttribute(mef_main_k, cudaFuncAttributeMaxDynamicSharedMemorySize, SMEM_TOTAL);
        attr_set = true;
    }

    lY_prepass<<<PREB, NT>>>(bunch, gwp);
    mef_main_k<<<dim3(WW / TW, HH / TH), NT, SMEM_TOTAL>>>(img, bunch, patch, qdst, gwp);
}

// round 4
// speedup vs baseline: 1.3878x; 1.0873x over previous
#include <cuda_runtime.h>
#include <cuda_fp16.h>
#include <math.h>

// ---------------- problem constants ----------------
#define HH      1024
#define WW      1024
#define NPIX    (HH * WW)
#define KK      8
#define WS      11
#define RAD     5

// ---------------- tiling ----------------
#define TW       32
#define TH       32
#define HTW      42            // TW + 2*RAD
#define HTH      42
#define HT       (HTW * HTH)   // 1764
#define NT       256
#define NLOAD    7             // ceil(HT / NT)
#define PREB     1024
#define MAINB    1024

// smem layout (bytes), all 16B-aligned
#define OFF_F01   0                      // float2[HT]      14112
#define OFF_F2    14112                  // float [HT]       7056
#define OFF_VB01  21168                  // float2[32*43]   11008
#define OFF_VB2   32176                  // float [32*43]    5504
#define OFF_OC01  37680                  // half2 [HT]       7056
#define OFF_OC2   44736                  // half  [HT]       3536 (padded)
#define OFF_GOFF  48272                  // int   [HT]       7056
#define SMEM_TOTAL 55328

struct GW { float w[WS]; };

// ---------------- scratch (static device globals; no allocation) ----------------
__device__ float g_lY_part[KK * PREB];
__device__ float g_lG[KK];
__device__ float g_q_part[MAINB];
__device__ int   g_done_pre  = 0;
__device__ int   g_done_main = 0;

// ======================= pass 1: lY / lG =======================
__global__ __launch_bounds__(NT) void lY_prepass(const float* __restrict__ bunch, GW gwp) {
    const float* gw = gwp.w;
    int tid = threadIdx.x;
    int idx = blockIdx.x * NT + tid;          // float4 index; PREB*NT == NPIX/4
    int y  = idx >> 8;
    int x0 = (idx & 255) << 2;

    float wy = 0.f;
#pragma unroll
    for (int j = 0; j < WS; j++) { int d = j - RAD; if ((unsigned)(y - d) < HH) wy += gw[j]; }
    float w[4];
#pragma unroll
    for (int e = 0; e < 4; e++) {
        int x = x0 + e;
        float wx = 0.f;
#pragma unroll
        for (int j = 0; j < WS; j++) { int d = j - RAD; if ((unsigned)(x - d) < WW) wx += gw[j]; }
        w[e] = wx * wy * (1.f / 3.f);
    }

    float acc[KK];
    const float4* b4 = (const float4*)bunch;
#pragma unroll
    for (int k = 0; k < KK; k++) {
        float4 a = b4[(size_t)(k * 3 + 0) * (NPIX / 4) + idx];
        float4 b = b4[(size_t)(k * 3 + 1) * (NPIX / 4) + idx];
        float4 c = b4[(size_t)(k * 3 + 2) * (NPIX / 4) + idx];
        acc[k] = w[0] * (a.x + b.x + c.x) + w[1] * (a.y + b.y + c.y)
               + w[2] * (a.z + b.z + c.z) + w[3] * (a.w + b.w + c.w);
    }

    __shared__ float red[NT];
#pragma unroll
    for (int k = 0; k < KK; k++) {
        red[tid] = acc[k];
        __syncthreads();
        for (int o = NT / 2; o > 0; o >>= 1) { if (tid < o) red[tid] += red[tid + o]; __syncthreads(); }
        if (tid == 0) g_lY_part[k * PREB + blockIdx.x] = red[0];
        __syncthreads();
    }

    __shared__ int isLast;
    if (tid == 0) {
        __threadfence();
        isLast = (atomicAdd(&g_done_pre, 1) == PREB - 1);
    }
    __syncthreads();
    if (isLast) {
        __threadfence();
        for (int k = 0; k < KK; k++) {
            float s = 0.f;
            for (int i = tid; i < PREB; i += NT) s += g_lY_part[k * PREB + i];
            red[tid] = s;
            __syncthreads();
            for (int o = NT / 2; o > 0; o >>= 1) { if (tid < o) red[tid] += red[tid + o]; __syncthreads(); }
            if (tid == 0) {
                double lY = (double)red[0] / (double)NPIX;
                double d = lY - 0.5;
                g_lG[k] = (float)exp(-(d * d) / 0.08);   // DENOM_G = 2*0.2^2
            }
            __syncthreads();
        }
        if (tid == 0) g_done_pre = 0;  // self-reset for next graph replay
    }
}

// ======================= separable blur helpers =======================
// Vertical: 6 consecutive output rows per task, 16 taps -> 2.67 loads/output.
__device__ __forceinline__ void vpass6(const float2* __restrict__ f01,
                                       const float* __restrict__ f2,
                                       float2* __restrict__ vb01,
                                       float* __restrict__ vb2,
                                       const float* gw, int tid) {
    if (tid < 252) {                        // 6 rowgroups * 42 cols
        int g = tid / 42, c = tid - g * 42;
        int r0 = g * 6;
        float ax[6], ay[6], az[6];
#pragma unroll
        for (int i = 0; i < 6; i++) { ax[i] = 0.f; ay[i] = 0.f; az[i] = 0.f; }
        const float2* p01 = f01 + r0 * HTW + c;
        const float*  p2  = f2  + r0 * HTW + c;
#pragma unroll
        for (int j = 0; j < 16; j++) {
            if (r0 + j < HTH) {
                float2 v = p01[j * HTW];
                float  z = p2[j * HTW];
#pragma unroll
                for (int i = 0; i < 6; i++) {
                    if (i <= j && j - i <= 10) {
                        float gg = gw[j - i];
                        ax[i] += gg * v.x; ay[i] += gg * v.y; az[i] += gg * z;
                    }
                }
            }
        }
#pragma unroll
        for (int i = 0; i < 6; i++) {
            int r = r0 + i;
            if (r < TH) {
                vb01[r * 43 + c] = make_float2(ax[i], ay[i]);
                vb2[r * 43 + c] = az[i];
            }
        }
    }
}

// Horizontal: lane = row (conflict-free: strides 43*8B and 43*4B), 4 cols/thread.
__device__ __forceinline__ void hpass(const float2* __restrict__ vb01,
                                      const float* __restrict__ vb2,
                                      const float* gw, int row, int x0, float3* out) {
    float ax[4], ay[4], az[4];
#pragma unroll
    for (int i = 0; i < 4; i++) { ax[i] = 0.f; ay[i] = 0.f; az[i] = 0.f; }
    const float2* p01 = vb01 + row * 43 + x0;
    const float*  p2  = vb2  + row * 43 + x0;
#pragma unroll
    for (int j = 0; j < 14; j++) {
        float2 v = p01[j];
        float  z = p2[j];
#pragma unroll
        for (int i = 0; i < 4; i++) {
            if (i <= j && j - i <= 10) {
                float gg = gw[j - i];
                ax[i] += gg * v.x; ay[i] += gg * v.y; az[i] += gg * z;
            }
        }
    }
#pragma unroll
    for (int i = 0; i < 4; i++) out[i] = make_float3(ax[i], ay[i], az[i]);
}

// ======================= main fused pass =======================
// Shifted domain v' = v - 0.5 (exact; reference zero-pads raw => padded v' = -0.5).
__global__ __launch_bounds__(NT, 4) void mef_main_k(
    const float* __restrict__ img,
    const float* __restrict__ bunch,
    float* __restrict__ patch_out,
    float* __restrict__ q_out,
    GW gwp)
{
    extern __shared__ char sm[];
    float2* s_f01  = (float2*)(sm + OFF_F01);
    float*  s_f2   = (float*)(sm + OFF_F2);
    float2* s_vb01 = (float2*)(sm + OFF_VB01);
    float*  s_vb2  = (float*)(sm + OFF_VB2);
    __half2* s_oc01 = (__half2*)(sm + OFF_OC01);
    __half*  s_oc2  = (__half*)(sm + OFF_OC2);
    int*    s_goff = (int*)(sm + OFF_GOFF);
    const float* gw = gwp.w;

    int tid = threadIdx.x;
    int tx = tid & 31, ty = tid >> 5;
    int bx = blockIdx.x, by = blockIdx.y;
    int gx0 = bx * TW - RAD, gy0 = by * TH - RAD;

    // ---- X pass: goff + output channels (shifted); oc stored half, f uses full fp32 ----
#pragma unroll
    for (int i = 0; i < NLOAD; i++) {
        int e = tid + i * NT;
        if (e < HT) {
            int hy = e / HTW, hx = e - hy * HTW;
            int gy = gy0 + hy, gx = gx0 + hx;
            int o = (((unsigned)gy < HH) && ((unsigned)gx < WW)) ? gy * WW + gx : -1;
            s_goff[e] = o;
            float o0 = -0.5f, o1 = -0.5f, o2 = -0.5f;
            if (o >= 0) {
                o0 = img[o] - 0.5f; o1 = img[NPIX + o] - 0.5f; o2 = img[2 * NPIX + o] - 0.5f;
            }
            s_oc01[e] = __floats2half2_rn(o0, o1);
            s_oc2[e]  = __float2half_rn(o2);
            s_f01[e] = make_float2((o0 + o1 + o2) * (1.f / 3.f),
                                   (o0 * o0 + o1 * o1 + o2 * o2) * (1.f / 3.f));
            s_f2[e] = 0.f;
        }
    }
    __syncthreads();

    int row = tx;           // thread's pixel row within tile
    int x0c = ty * 4;       // thread's 4 consecutive pixel cols

    vpass6(s_f01, s_f2, s_vb01, s_vb2, gw, tid);
    __syncthreads();
    float3 xo[4];
    hpass(s_vb01, s_vb2, gw, row, x0c, xo);
    float muXs[4], sX2[4];
#pragma unroll
    for (int i = 0; i < 4; i++) { muXs[i] = xo[i].x; sX2[i] = xo[i].y - muXs[i] * muXs[i]; }

    float best[4], bestXY[4], num[4], den[4];
    int pidx[4];
#pragma unroll
    for (int i = 0; i < 4; i++) {
        best[i] = -1e30f; bestXY[i] = 0.f; num[i] = 0.f; den[i] = 0.f; pidx[i] = 0;
    }

    for (int k = 0; k < KK; k++) {
        const float* bb = bunch + (size_t)(3 * k) * NPIX;
        __syncthreads();    // pack free (vpass of prev k done) & vb consumed
#pragma unroll
        for (int i = 0; i < NLOAD; i++) {
            int e = tid + i * NT;
            if (e < HT) {
                int o = s_goff[e];
                float v0 = -0.5f, v1 = -0.5f, v2 = -0.5f;
                if (o >= 0) {
                    v0 = bb[o] - 0.5f; v1 = bb[NPIX + o] - 0.5f; v2 = bb[2 * NPIX + o] - 0.5f;
                }
                float2 o01 = __half22float2(s_oc01[e]);
                float  o2  = __half2float(s_oc2[e]);
                s_f01[e] = make_float2((v0 + v1 + v2) * (1.f / 3.f),
                                       (v0 * v0 + v1 * v1 + v2 * v2) * (1.f / 3.f));
                s_f2[e]  = (v0 * o01.x + v1 * o01.y + v2 * o2) * (1.f / 3.f);
            }
        }
        __syncthreads();    // pack ready
        vpass6(s_f01, s_f2, s_vb01, s_vb2, gw, tid);
        __syncthreads();    // vb ready
        float3 yo[4];
        hpass(s_vb01, s_vb2, gw, row, x0c, yo);

        float lGk = g_lG[k];
#pragma unroll
        for (int i = 0; i < 4; i++) {
            float muYs = yo[i].x;
            float sY2 = yo[i].y - muYs * muYs;
            float sXY = yo[i].z - muXs[i] * muYs;
            if (sY2 > best[i]) { best[i] = sY2; bestXY[i] = sXY; pidx[i] = k; }
            float muY = muYs + 0.5f;
            float wgt = lGk * __expf(-(muYs * muYs) * (1.f / 0.08f));  // DENOM_L
            num[i] += wgt * muY;
            den[i] += wgt;
        }
        // no trailing sync: next iteration's first sync orders vb reuse
    }

    // ---- epilogue ----
    __syncthreads();
    float qsum = 0.f;
    float* sidx = (float*)s_vb01;   // reuse: 1024 floats
#pragma unroll
    for (int i = 0; i < 4; i++) {
        float muX  = muXs[i] + 0.5f;
        float muYb = num[i] / den[i];
        float l  = (2.f * muX * muYb + 1e-4f) /
                   fmaxf(muX * muX + muYb * muYb + 1e-4f, 1e-6f);      // C1 = 0.01^2
        float cs = (2.f * bestXY[i] + 9e-4f) /
                   fmaxf(sX2[i] + best[i] + 9e-4f, 1e-6f);              // C2 = 0.03^2
        qsum += l * cs;
        sidx[row * 32 + x0c + i] = (float)pidx[i];
    }
    __syncthreads();
    if (patch_out) {
#pragma unroll
        for (int i = 0; i < 4; i++) {
            int rr = ty + 8 * i;
            patch_out[(by * TH + rr) * WW + bx * TW + tx] = sidx[rr * 32 + tx];
        }
    }

    // ---- deterministic q reduction: block tree + last-block fold ----
    float* qred = (float*)s_f01;
    qred[tid] = qsum;
    __syncthreads();
    for (int o = NT / 2; o > 0; o >>= 1) { if (tid < o) qred[tid] += qred[tid + o]; __syncthreads(); }
    if (tid == 0) g_q_part[by * gridDim.x + bx] = qred[0];

    __shared__ int isLast;
    if (tid == 0) {
        __threadfence();
        isLast = (atomicAdd(&g_done_main, 1) == MAINB - 1);
    }
    __syncthreads();
    if (isLast) {
        __threadfence();
        float s = 0.f;
        for (int i = tid; i < MAINB; i += NT) s += g_q_part[i];
        qred[tid] = s;
        __syncthreads();
        for (int o = NT / 2; o > 0; o >>= 1) { if (tid < o) qred[tid] += qred[tid + o]; __syncthreads(); }
        if (tid == 0) {
            if (q_out) q_out[0] = qred[0] / (float)NPIX;
            g_done_main = 0;
        }
    }
}

// ---------------- launch ----------------
extern "C" void kernel_launch(void* const* d_in, const int* in_sizes, int n_in,
                              void* d_out, int out_size) {
    const float* a = (const float*)d_in[0];
    const float* b = (const float*)d_in[1];
    const float* img;
    const float* bunch;
    if (in_sizes[0] > in_sizes[1]) { bunch = a; img = b; }
    else                           { img = a;  bunch = b; }

    float* out = (float*)d_out;
    float* qdst = nullptr;
    float* patch = nullptr;
    if (out_size >= NPIX + 1)      { qdst = out; patch = out + 1; }
    else if (out_size == NPIX)     { patch = out; }
    else                           { qdst = out; }

    // host-side double-precision gaussian window
    GW gwp;
    {
        double t[WS], s = 0.0;
        double sg = (double)WS / 6.0;
        for (int i = 0; i < WS; i++) {
            double d = (double)(i - RAD);
            t[i] = exp(-(d * d) / (2.0 * sg * sg));
            s += t[i];
        }
        for (int i = 0; i < WS; i++) gwp.w[i] = (float)(t[i] / s);
    }

    static bool attr_set = false;
    if (!attr_set) {
        cudaFuncSetAttribute(mef_main_k, cudaFuncAttributeMaxDynamicSharedMemorySize, SMEM_TOTAL);
        attr_set = true;
    }

    lY_prepass<<<PREB, NT>>>(bunch, gwp);
    mef_main_k<<<dim3(WW / TW, HH / TH), NT, SMEM_TOTAL>>>(img, bunch, patch, qdst, gwp);
}

// round 6
// speedup vs baseline: 1.3897x; 1.0014x over previous
#include <cuda_runtime.h>
#include <cuda_fp16.h>
#include <math.h>

// ---------------- problem constants ----------------
#define HH      1024
#define WW      1024
#define NPIX    (HH * WW)
#define KK      8
#define WS      11
#define RAD     5

// ---------------- main tiling: 64 x 32 tiles, 512 threads ----------------
#define TW       64
#define TH       32
#define HTW      74            // TW + 2*RAD
#define HTH      42            // TH + 2*RAD
#define HT       (HTW * HTH)   // 3108
#define NT2      512
#define NLOAD    7             // ceil(HT / NT2)
#define VBW      75            // vb row stride (float2 / float units)
#define MAINB    512           // (1024/64)*(1024/32)

// prepass
#define NT       256
#define PREB     1024

// smem layout (bytes), 16B-aligned
#define OFF_F01   0                       // float2[HT]      24864
#define OFF_F2    24864                   // float [HT]      12432
#define OFF_VB01  37296                   // float2[32*75]   19200
#define OFF_VB2   56496                   // float [32*75]    9600
#define SMEM_TOTAL 66096

struct GW { float w[WS]; };

// ---------------- scratch (static device globals; no allocation) ----------------
__device__ float g_lY_part[KK * PREB];
__device__ float g_lG[KK];
__device__ float g_q_part[MAINB];
__device__ int   g_done_pre  = 0;
__device__ int   g_done_main = 0;

// ======================= pass 1: lY / lG =======================
// mean(blur(s)) = (1/HW)*sum_p s[p]*Wx(x)*Wy(y). Last block folds + computes lG.
__global__ __launch_bounds__(NT) void lY_prepass(const float* __restrict__ bunch, GW gwp) {
    const float* gw = gwp.w;
    int tid = threadIdx.x;
    int idx = blockIdx.x * NT + tid;          // float4 index; PREB*NT == NPIX/4
    int y  = idx >> 8;
    int x0 = (idx & 255) << 2;

    float wy = 0.f;
#pragma unroll
    for (int j = 0; j < WS; j++) { int d = j - RAD; if ((unsigned)(y - d) < HH) wy += gw[j]; }
    float w[4];
#pragma unroll
    for (int e = 0; e < 4; e++) {
        int x = x0 + e;
        float wx = 0.f;
#pragma unroll
        for (int j = 0; j < WS; j++) { int d = j - RAD; if ((unsigned)(x - d) < WW) wx += gw[j]; }
        w[e] = wx * wy * (1.f / 3.f);
    }

    float acc[KK];
    const float4* b4 = (const float4*)bunch;
#pragma unroll
    for (int k = 0; k < KK; k++) {
        float4 a = b4[(size_t)(k * 3 + 0) * (NPIX / 4) + idx];
        float4 b = b4[(size_t)(k * 3 + 1) * (NPIX / 4) + idx];
        float4 c = b4[(size_t)(k * 3 + 2) * (NPIX / 4) + idx];
        acc[k] = w[0] * (a.x + b.x + c.x) + w[1] * (a.y + b.y + c.y)
               + w[2] * (a.z + b.z + c.z) + w[3] * (a.w + b.w + c.w);
    }

    __shared__ float red[NT];
#pragma unroll
    for (int k = 0; k < KK; k++) {
        red[tid] = acc[k];
        __syncthreads();
        for (int o = NT / 2; o > 0; o >>= 1) { if (tid < o) red[tid] += red[tid + o]; __syncthreads(); }
        if (tid == 0) g_lY_part[k * PREB + blockIdx.x] = red[0];
        __syncthreads();
    }

    __shared__ int isLast;
    if (tid == 0) {
        __threadfence();
        isLast = (atomicAdd(&g_done_pre, 1) == PREB - 1);
    }
    __syncthreads();
    if (isLast) {
        __threadfence();
        for (int k = 0; k < KK; k++) {
            float s = 0.f;
            for (int i = tid; i < PREB; i += NT) s += g_lY_part[k * PREB + i];
            red[tid] = s;
            __syncthreads();
            for (int o = NT / 2; o > 0; o >>= 1) { if (tid < o) red[tid] += red[tid + o]; __syncthreads(); }
            if (tid == 0) {
                double lY = (double)red[0] / (double)NPIX;
                double d = lY - 0.5;
                g_lG[k] = (float)exp(-(d * d) / 0.08);   // DENOM_G = 2*0.2^2
            }
            __syncthreads();
        }
        if (tid == 0) g_done_pre = 0;  // self-reset for next graph replay
    }
}

// ======================= separable blur helpers =======================
// Vertical: 6 consecutive output rows per task, 16 taps -> 2.67 loads/output.
// 444 tasks (6 rowgroups x 74 cols) over 512 threads.
__device__ __forceinline__ void vpass6(const float2* __restrict__ f01,
                                       const float* __restrict__ f2,
                                       float2* __restrict__ vb01,
                                       float* __restrict__ vb2,
                                       const float* gw, int tid) {
    if (tid < 444) {
        int g = tid / HTW, c = tid - g * HTW;
        int r0 = g * 6;
        float ax[6], ay[6], az[6];
#pragma unroll
        for (int i = 0; i < 6; i++) { ax[i] = 0.f; ay[i] = 0.f; az[i] = 0.f; }
        const float2* p01 = f01 + r0 * HTW + c;
        const float*  p2  = f2  + r0 * HTW + c;
#pragma unroll
        for (int j = 0; j < 16; j++) {
            if (r0 + j < HTH) {
                float2 v = p01[j * HTW];
                float  z = p2[j * HTW];
#pragma unroll
                for (int i = 0; i < 6; i++) {
                    if (i <= j && j - i <= 10) {
                        float gg = gw[j - i];
                        ax[i] += gg * v.x; ay[i] += gg * v.y; az[i] += gg * z;
                    }
                }
            }
        }
#pragma unroll
        for (int i = 0; i < 6; i++) {
            int r = r0 + i;
            if (r < TH) {
                vb01[r * VBW + c] = make_float2(ax[i], ay[i]);
                vb2[r * VBW + c] = az[i];
            }
        }
    }
}

// Horizontal: lane = row (strides verified conflict-free), 4 cols/thread.
__device__ __forceinline__ void hpass(const float2* __restrict__ vb01,
                                      const float* __restrict__ vb2,
                                      const float* gw, int row, int x0, float3* out) {
    float ax[4], ay[4], az[4];
#pragma unroll
    for (int i = 0; i < 4; i++) { ax[i] = 0.f; ay[i] = 0.f; az[i] = 0.f; }
    const float2* p01 = vb01 + row * VBW + x0;
    const float*  p2  = vb2  + row * VBW + x0;
#pragma unroll
    for (int j = 0; j < 14; j++) {
        float2 v = p01[j];
        float  z = p2[j];
#pragma unroll
        for (int i = 0; i < 4; i++) {
            if (i <= j && j - i <= 10) {
                float gg = gw[j - i];
                ax[i] += gg * v.x; ay[i] += gg * v.y; az[i] += gg * z;
            }
        }
    }
#pragma unroll
    for (int i = 0; i < 4; i++) out[i] = make_float3(ax[i], ay[i], az[i]);
}

// ======================= main fused pass =======================
// Shifted domain v' = v - 0.5 (exact; reference zero-pads raw => padded v' = -0.5).
__global__ __launch_bounds__(NT2, 2) void mef_main_k(
    const float* __restrict__ img,
    const float* __restrict__ bunch,
    float* __restrict__ patch_out,
    float* __restrict__ q_out,
    GW gwp)
{
    extern __shared__ char sm[];
    float2* s_f01  = (float2*)(sm + OFF_F01);
    float*  s_f2   = (float*)(sm + OFF_F2);
    float2* s_vb01 = (float2*)(sm + OFF_VB01);
    float*  s_vb2  = (float*)(sm + OFF_VB2);
    const float* gw = gwp.w;

    int tid = threadIdx.x;
    int row = tid & 31;          // hpass: output row
    int x0c = (tid >> 5) * 4;    // hpass: 4 consecutive output cols
    int bx = blockIdx.x, by = blockIdx.y;
    int gx0 = bx * TW - RAD, gy0 = by * TH - RAD;

    // per-thread halo state: global offsets + output-image channels (half regs)
    int goff[NLOAD];
    __half2 h01[NLOAD];          // (o0', o1')
    __half2 h2p[4];              // o2' packed pairs

#pragma unroll
    for (int i = 0; i < NLOAD; i++) {
        int e = tid + i * NT2;
        float o0 = -0.5f, o1 = -0.5f, o2 = -0.5f;
        int o = -2;
        if (e < HT) {
            int hy = e / HTW, hx = e - hy * HTW;
            int gy = gy0 + hy, gx = gx0 + hx;
            o = (((unsigned)gy < HH) && ((unsigned)gx < WW)) ? gy * WW + gx : -1;
            if (o >= 0) {
                o0 = img[o] - 0.5f; o1 = img[NPIX + o] - 0.5f; o2 = img[2 * NPIX + o] - 0.5f;
            }
            s_f01[e] = make_float2((o0 + o1 + o2) * (1.f / 3.f),
                                   (o0 * o0 + o1 * o1 + o2 * o2) * (1.f / 3.f));
            s_f2[e] = 0.f;
        }
        goff[i] = o;
        h01[i] = __floats2half2_rn(o0, o1);
        __half h2v = __float2half_rn(o2);
        if (i & 1) h2p[i >> 1] = __halves2half2(__low2half(h2p[i >> 1]), h2v);
        else       h2p[i >> 1] = __halves2half2(h2v, __high2half(h2p[i >> 1]));
    }
    __syncthreads();

    vpass6(s_f01, s_f2, s_vb01, s_vb2, gw, tid);
    __syncthreads();
    float3 xo[4];
    hpass(s_vb01, s_vb2, gw, row, x0c, xo);
    float muXs[4], sX2[4];
#pragma unroll
    for (int i = 0; i < 4; i++) { muXs[i] = xo[i].x; sX2[i] = xo[i].y - muXs[i] * muXs[i]; }

    float best[4], bestXY[4], num[4], den[4];
    int pidx[4];
#pragma unroll
    for (int i = 0; i < 4; i++) {
        best[i] = -1e30f; bestXY[i] = 0.f; num[i] = 0.f; den[i] = 0.f; pidx[i] = 0;
    }

    for (int k = 0; k < KK; k++) {
        const float* bb = bunch + (size_t)(3 * k) * NPIX;
        __syncthreads();    // pack free (vpass of prev k done) & vb consumed
#pragma unroll
        for (int i = 0; i < NLOAD; i++) {
            int e = tid + i * NT2;
            if (e < HT) {
                int o = goff[i];
                float v0 = -0.5f, v1 = -0.5f, v2 = -0.5f;
                if (o >= 0) {
                    v0 = bb[o] - 0.5f; v1 = bb[NPIX + o] - 0.5f; v2 = bb[2 * NPIX + o] - 0.5f;
                }
                float2 o01 = __half22float2(h01[i]);
                float  o2  = __half2float((i & 1) ? __high2half(h2p[i >> 1])
                                                  : __low2half(h2p[i >> 1]));
                s_f01[e] = make_float2((v0 + v1 + v2) * (1.f / 3.f),
                                       (v0 * v0 + v1 * v1 + v2 * v2) * (1.f / 3.f));
                s_f2[e]  = (v0 * o01.x + v1 * o01.y + v2 * o2) * (1.f / 3.f);
            }
        }
        __syncthreads();    // pack ready
        vpass6(s_f01, s_f2, s_vb01, s_vb2, gw, tid);
        __syncthreads();    // vb ready
        float3 yo[4];
        hpass(s_vb01, s_vb2, gw, row, x0c, yo);

        float lGk = g_lG[k];
#pragma unroll
        for (int i = 0; i < 4; i++) {
            float muYs = yo[i].x;
            float sY2 = yo[i].y - muYs * muYs;
            float sXY = yo[i].z - muXs[i] * muYs;
            if (sY2 > best[i]) { best[i] = sY2; bestXY[i] = sXY; pidx[i] = k; }
            float muY = muYs + 0.5f;
            float wgt = lGk * __expf(-(muYs * muYs) * (1.f / 0.08f));  // DENOM_L
            num[i] += wgt * muY;
            den[i] += wgt;
        }
        // no trailing sync: next iteration's first sync orders vb reuse
    }

    // ---- epilogue ----
    __syncthreads();
    float qsum = 0.f;
    float* sidx = (float*)s_vb01;   // staging: 32 x 64 floats
#pragma unroll
    for (int i = 0; i < 4; i++) {
        float muX  = muXs[i] + 0.5f;
        float muYb = num[i] / den[i];
        float l  = (2.f * muX * muYb + 1e-4f) /
                   fmaxf(muX * muX + muYb * muYb + 1e-4f, 1e-6f);      // C1 = 0.01^2
        float cs = (2.f * bestXY[i] + 9e-4f) /
                   fmaxf(sX2[i] + best[i] + 9e-4f, 1e-6f);              // C2 = 0.03^2
        qsum += l * cs;
        sidx[row * 64 + x0c + i] = (float)pidx[i];
    }
    __syncthreads();
    if (patch_out) {
        // scalar stores: patch_out base is only 4B-aligned (out + 1), so no
        // vector STG. Thread t writes 4 consecutive pixels -> warps still emit
        // contiguous 512B spans, fully coalesced at the 32B-sector level.
        int px = tid * 4;
        int rr = px >> 6, cc = px & 63;
        float* dst = &patch_out[(by * TH + rr) * WW + bx * TW + cc];
        const float* src = &sidx[px];
        dst[0] = src[0]; dst[1] = src[1]; dst[2] = src[2]; dst[3] = src[3];
    }

    // ---- deterministic q reduction: block tree + last-block fold ----
    float* qred = (float*)s_f01;
    qred[tid] = qsum;
    __syncthreads();
    for (int o = NT2 / 2; o > 0; o >>= 1) { if (tid < o) qred[tid] += qred[tid + o]; __syncthreads(); }
    if (tid == 0) g_q_part[by * gridDim.x + bx] = qred[0];

    __shared__ int isLast;
    if (tid == 0) {
        __threadfence();
        isLast = (atomicAdd(&g_done_main, 1) == MAINB - 1);
    }
    __syncthreads();
    if (isLast) {
        __threadfence();
        float s = (tid < MAINB) ? g_q_part[tid] : 0.f;
        qred[tid] = s;
        __syncthreads();
        for (int o = NT2 / 2; o > 0; o >>= 1) { if (tid < o) qred[tid] += qred[tid + o]; __syncthreads(); }
        if (tid == 0) {
            if (q_out) q_out[0] = qred[0] / (float)NPIX;
            g_done_main = 0;
        }
    }
}

// ---------------- launch ----------------
extern "C" void kernel_launch(void* const* d_in, const int* in_sizes, int n_in,
                              void* d_out, int out_size) {
    const float* a = (const float*)d_in[0];
    const float* b = (const float*)d_in[1];
    const float* img;
    const float* bunch;
    if (in_sizes[0] > in_sizes[1]) { bunch = a; img = b; }
    else                           { img = a;  bunch = b; }

    float* out = (float*)d_out;
    float* qdst = nullptr;
    float* patch = nullptr;
    if (out_size >= NPIX + 1)      { qdst = out; patch = out + 1; }
    else if (out_size == NPIX)     { patch = out; }
    else                           { qdst = out; }

    // host-side double-precision gaussian window
    GW gwp;
    {
        double t[WS], s = 0.0;
        double sg = (double)WS / 6.0;
        for (int i = 0; i < WS; i++) {
            double d = (double)(i - RAD);
            t[i] = exp(-(d * d) / (2.0 * sg * sg));
            s += t[i];
        }
        for (int i = 0; i < WS; i++) gwp.w[i] = (float)(t[i] / s);
    }

    static bool attr_set = false;
    if (!attr_set) {
        cudaFuncSetAttribute(mef_main_k, cudaFuncAttributeMaxDynamicSharedMemorySize, SMEM_TOTAL);
        attr_set = true;
    }

    lY_prepass<<<PREB, NT>>>(bunch, gwp);
    mef_main_k<<<dim3(WW / TW, HH / TH), NT2, SMEM_TOTAL>>>(img, bunch, patch, qdst, gwp);
}

// round 7
// speedup vs baseline: 1.4972x; 1.0773x over previous
#include <cuda_runtime.h>
#include <cuda_fp16.h>
#include <math.h>

// ---------------- problem constants ----------------
#define HH      1024
#define WW      1024
#define NPIX    (HH * WW)
#define KK      8
#define WS      11
#define RAD     5

// ---------------- main tiling: 64 x 32 tiles, 512 threads ----------------
#define TW       64
#define TH       32
#define HTW      74            // TW + 2*RAD
#define HTH      42            // TH + 2*RAD
#define HT       (HTW * HTH)   // 3108
#define NT2      512
#define NLOAD    7             // ceil(HT / NT2)
#define VBW      75            // vb row stride (float2 / float units)
#define MAINB    512           // (1024/64)*(1024/32)

// prepass
#define NT       256
#define PREB     1024

// smem layout (bytes), 16B-aligned
#define OFF_F01   0                       // float2[HT]      24864
#define OFF_F2    24864                   // float [HT]      12432
#define OFF_VB01  37296                   // float2[32*75]   19200
#define OFF_VB2   56496                   // float [32*75]    9600
#define SMEM_TOTAL 66096

struct GW { float w[WS]; };

// ---------------- scratch (static device globals; no allocation) ----------------
__device__ float g_lY_part[KK * PREB];
__device__ float g_lG[KK];
__device__ float g_q_part[MAINB];
__device__ int   g_done_pre  = 0;
__device__ int   g_done_main = 0;

// ======================= pass 1: lY / lG =======================
// mean(blur(s)) = (1/HW)*sum_p s[p]*Wx(x)*Wy(y). Last block folds + computes lG.
__global__ __launch_bounds__(NT) void lY_prepass(const float* __restrict__ bunch, GW gwp) {
    const float* gw = gwp.w;
    int tid = threadIdx.x;
    int lane = tid & 31, wid = tid >> 5;
    int idx = blockIdx.x * NT + tid;          // float4 index; PREB*NT == NPIX/4
    int y  = idx >> 8;
    int x0 = (idx & 255) << 2;

    float wy = 0.f;
#pragma unroll
    for (int j = 0; j < WS; j++) { int d = j - RAD; if ((unsigned)(y - d) < HH) wy += gw[j]; }
    float w[4];
#pragma unroll
    for (int e = 0; e < 4; e++) {
        int x = x0 + e;
        float wx = 0.f;
#pragma unroll
        for (int j = 0; j < WS; j++) { int d = j - RAD; if ((unsigned)(x - d) < WW) wx += gw[j]; }
        w[e] = wx * wy * (1.f / 3.f);
    }

    float acc[KK];
    const float4* b4 = (const float4*)bunch;
#pragma unroll
    for (int k = 0; k < KK; k++) {
        float4 a = b4[(size_t)(k * 3 + 0) * (NPIX / 4) + idx];
        float4 b = b4[(size_t)(k * 3 + 1) * (NPIX / 4) + idx];
        float4 c = b4[(size_t)(k * 3 + 2) * (NPIX / 4) + idx];
        acc[k] = w[0] * (a.x + b.x + c.x) + w[1] * (a.y + b.y + c.y)
               + w[2] * (a.z + b.z + c.z) + w[3] * (a.w + b.w + c.w);
    }

    // warp butterfly per k, one syncthreads, warp-0 cross-warp fold
    __shared__ float red[NT];                 // reused: [warp*8+k] partials
#pragma unroll
    for (int k = 0; k < KK; k++) {
#pragma unroll
        for (int o = 16; o > 0; o >>= 1) acc[k] += __shfl_xor_sync(0xffffffffu, acc[k], o);
        if (lane == 0) red[wid * 8 + k] = acc[k];
    }
    __syncthreads();
    if (tid < 32) {
        int k = tid & 7, w0 = tid >> 3;       // w0 in 0..3
        float v = red[w0 * 8 + k] + red[(w0 + 4) * 8 + k];
        v += __shfl_xor_sync(0xffffffffu, v, 8);    // fold w0^1
        v += __shfl_xor_sync(0xffffffffu, v, 16);   // fold w0^2
        if (tid < 8) g_lY_part[k * PREB + blockIdx.x] = v;
    }

    __shared__ int isLast;
    if (tid == 0) {
        __threadfence();
        isLast = (atomicAdd(&g_done_pre, 1) == PREB - 1);
    }
    __syncthreads();
    if (isLast) {
        __threadfence();
        for (int k = 0; k < KK; k++) {
            float s = 0.f;
            for (int i = tid; i < PREB; i += NT) s += g_lY_part[k * PREB + i];
            red[tid] = s;
            __syncthreads();
            for (int o = NT / 2; o > 0; o >>= 1) { if (tid < o) red[tid] += red[tid + o]; __syncthreads(); }
            if (tid == 0) {
                double lY = (double)red[0] / (double)NPIX;
                double d = lY - 0.5;
                g_lG[k] = (float)exp(-(d * d) / 0.08);   // DENOM_G = 2*0.2^2
            }
            __syncthreads();
        }
        if (tid == 0) g_done_pre = 0;  // self-reset for next graph replay
    }
}

// ======================= separable blur helpers =======================
// Vertical: 6 consecutive output rows per task, 16 taps -> 2.67 loads/output.
__device__ __forceinline__ void vpass6(const float2* __restrict__ f01,
                                       const float* __restrict__ f2,
                                       float2* __restrict__ vb01,
                                       float* __restrict__ vb2,
                                       const float* gw, int tid) {
    if (tid < 444) {
        int g = tid / HTW, c = tid - g * HTW;
        int r0 = g * 6;
        float ax[6], ay[6], az[6];
#pragma unroll
        for (int i = 0; i < 6; i++) { ax[i] = 0.f; ay[i] = 0.f; az[i] = 0.f; }
        const float2* p01 = f01 + r0 * HTW + c;
        const float*  p2  = f2  + r0 * HTW + c;
#pragma unroll
        for (int j = 0; j < 16; j++) {
            if (r0 + j < HTH) {
                float2 v = p01[j * HTW];
                float  z = p2[j * HTW];
#pragma unroll
                for (int i = 0; i < 6; i++) {
                    if (i <= j && j - i <= 10) {
                        float gg = gw[j - i];
                        ax[i] += gg * v.x; ay[i] += gg * v.y; az[i] += gg * z;
                    }
                }
            }
        }
#pragma unroll
        for (int i = 0; i < 6; i++) {
            int r = r0 + i;
            if (r < TH) {
                vb01[r * VBW + c] = make_float2(ax[i], ay[i]);
                vb2[r * VBW + c] = az[i];
            }
        }
    }
}

// Horizontal: lane = row (strides verified conflict-free), 4 cols/thread.
__device__ __forceinline__ void hpass(const float2* __restrict__ vb01,
                                      const float* __restrict__ vb2,
                                      const float* gw, int row, int x0, float3* out) {
    float ax[4], ay[4], az[4];
#pragma unroll
    for (int i = 0; i < 4; i++) { ax[i] = 0.f; ay[i] = 0.f; az[i] = 0.f; }
    const float2* p01 = vb01 + row * VBW + x0;
    const float*  p2  = vb2  + row * VBW + x0;
#pragma unroll
    for (int j = 0; j < 14; j++) {
        float2 v = p01[j];
        float  z = p2[j];
#pragma unroll
        for (int i = 0; i < 4; i++) {
            if (i <= j && j - i <= 10) {
                float gg = gw[j - i];
                ax[i] += gg * v.x; ay[i] += gg * v.y; az[i] += gg * z;
            }
        }
    }
#pragma unroll
    for (int i = 0; i < 4; i++) out[i] = make_float3(ax[i], ay[i], az[i]);
}

// Pack-write: load bunch k tile (shifted), build (s, s², s·o') fields.
__device__ __forceinline__ void pack_write(const float* __restrict__ bb,
                                           const int* goff, const __half2* h01,
                                           const __half2* h2p,
                                           float2* __restrict__ s_f01,
                                           float* __restrict__ s_f2, int tid) {
#pragma unroll
    for (int i = 0; i < NLOAD; i++) {
        int e = tid + i * NT2;
        if (e < HT) {
            int o = goff[i];
            float v0 = -0.5f, v1 = -0.5f, v2 = -0.5f;
            if (o >= 0) {
                v0 = bb[o] - 0.5f; v1 = bb[NPIX + o] - 0.5f; v2 = bb[2 * NPIX + o] - 0.5f;
            }
            float2 o01 = __half22float2(h01[i]);
            float  o2  = __half2float((i & 1) ? __high2half(h2p[i >> 1])
                                              : __low2half(h2p[i >> 1]));
            s_f01[e] = make_float2((v0 + v1 + v2) * (1.f / 3.f),
                                   (v0 * v0 + v1 * v1 + v2 * v2) * (1.f / 3.f));
            s_f2[e]  = (v0 * o01.x + v1 * o01.y + v2 * o2) * (1.f / 3.f);
        }
    }
}

// ======================= main fused pass =======================
// Shifted domain v' = v - 0.5 (exact; reference zero-pads raw => padded v' = -0.5).
__global__ __launch_bounds__(NT2, 2) void mef_main_k(
    const float* __restrict__ img,
    const float* __restrict__ bunch,
    float* __restrict__ patch_out,
    float* __restrict__ q_out,
    GW gwp)
{
    extern __shared__ char sm[];
    float2* s_f01  = (float2*)(sm + OFF_F01);
    float*  s_f2   = (float*)(sm + OFF_F2);
    float2* s_vb01 = (float2*)(sm + OFF_VB01);
    float*  s_vb2  = (float*)(sm + OFF_VB2);
    const float* gw = gwp.w;

    int tid = threadIdx.x;
    int lane = tid & 31;
    int row = tid & 31;          // hpass: output row
    int x0c = (tid >> 5) * 4;    // hpass: 4 consecutive output cols
    int bx = blockIdx.x, by = blockIdx.y;
    int gx0 = bx * TW - RAD, gy0 = by * TH - RAD;

    // per-thread halo state: global offsets + output-image channels (half regs)
    int goff[NLOAD];
    __half2 h01[NLOAD];          // (o0', o1')
    __half2 h2p[4];              // o2' packed pairs
#pragma unroll
    for (int i = 0; i < 4; i++) h2p[i] = __halves2half2(__float2half(0.f), __float2half(0.f));

#pragma unroll
    for (int i = 0; i < NLOAD; i++) {
        int e = tid + i * NT2;
        float o0 = -0.5f, o1 = -0.5f, o2 = -0.5f;
        int o = -2;
        if (e < HT) {
            int hy = e / HTW, hx = e - hy * HTW;
            int gy = gy0 + hy, gx = gx0 + hx;
            o = (((unsigned)gy < HH) && ((unsigned)gx < WW)) ? gy * WW + gx : -1;
            if (o >= 0) {
                o0 = img[o] - 0.5f; o1 = img[NPIX + o] - 0.5f; o2 = img[2 * NPIX + o] - 0.5f;
            }
            s_f01[e] = make_float2((o0 + o1 + o2) * (1.f / 3.f),
                                   (o0 * o0 + o1 * o1 + o2 * o2) * (1.f / 3.f));
            s_f2[e] = 0.f;
        }
        goff[i] = o;
        h01[i] = __floats2half2_rn(o0, o1);
        __half h2v = __float2half_rn(o2);
        if (i & 1) h2p[i >> 1] = __halves2half2(__low2half(h2p[i >> 1]), h2v);
        else       h2p[i >> 1] = __halves2half2(h2v, __high2half(h2p[i >> 1]));
    }
    __syncthreads();

    vpass6(s_f01, s_f2, s_vb01, s_vb2, gw, tid);
    __syncthreads();                 // vb ready; pack free
    float3 xo[4];
    hpass(s_vb01, s_vb2, gw, row, x0c, xo);
    float muXs[4], sX2[4];
#pragma unroll
    for (int i = 0; i < 4; i++) { muXs[i] = xo[i].x; sX2[i] = xo[i].y - muXs[i] * muXs[i]; }

    // write pack for k=0 while other warps still in hpass (same barrier interval)
    pack_write(bunch, goff, h01, h2p, s_f01, s_f2, tid);
    __syncthreads();                 // pack(0) ready; vb consumed

    float best[4], bestXY[4], num[4], den[4];
    int pidx[4];
#pragma unroll
    for (int i = 0; i < 4; i++) {
        best[i] = -1e30f; bestXY[i] = 0.f; num[i] = 0.f; den[i] = 0.f; pidx[i] = 0;
    }

    for (int k = 0; k < KK; k++) {
        vpass6(s_f01, s_f2, s_vb01, s_vb2, gw, tid);
        __syncthreads();             // vb ready; pack free
        float3 yo[4];
        hpass(s_vb01, s_vb2, gw, row, x0c, yo);

        float lGk = g_lG[k];
#pragma unroll
        for (int i = 0; i < 4; i++) {
            float muYs = yo[i].x;
            float sY2 = yo[i].y - muYs * muYs;
            float sXY = yo[i].z - muXs[i] * muYs;
            if (sY2 > best[i]) { best[i] = sY2; bestXY[i] = sXY; pidx[i] = k; }
            float muY = muYs + 0.5f;
            float wgt = lGk * __expf(-(muYs * muYs) * (1.f / 0.08f));  // DENOM_L
            num[i] += wgt * muY;
            den[i] += wgt;
        }
        // prefetch + pack next exposure, overlapping hpass/stat issue stream
        if (k < KK - 1)
            pack_write(bunch + (size_t)(3 * (k + 1)) * NPIX, goff, h01, h2p,
                       s_f01, s_f2, tid);
        __syncthreads();             // pack(k+1) ready; vb consumed
    }

    // ---- epilogue ----
    float qsum = 0.f;
    float* sidx = (float*)s_vb01;   // staging: 32 x 64 floats
#pragma unroll
    for (int i = 0; i < 4; i++) {
        float muX  = muXs[i] + 0.5f;
        float muYb = num[i] / den[i];
        float l  = (2.f * muX * muYb + 1e-4f) /
                   fmaxf(muX * muX + muYb * muYb + 1e-4f, 1e-6f);      // C1 = 0.01^2
        float cs = (2.f * bestXY[i] + 9e-4f) /
                   fmaxf(sX2[i] + best[i] + 9e-4f, 1e-6f);              // C2 = 0.03^2
        qsum += l * cs;
        sidx[row * 64 + x0c + i] = (float)pidx[i];
    }
    __syncthreads();
    if (patch_out) {
        // scalar stores: patch_out base is only 4B-aligned (out + 1).
        int px = tid * 4;
        int rr = px >> 6, cc = px & 63;
        float* dst = &patch_out[(by * TH + rr) * WW + bx * TW + cc];
        const float* src = &sidx[px];
        dst[0] = src[0]; dst[1] = src[1]; dst[2] = src[2]; dst[3] = src[3];
    }

    // ---- deterministic q reduction: shuffle tree + last-block fold ----
    __shared__ float qw[16];
#pragma unroll
    for (int o = 16; o > 0; o >>= 1) qsum += __shfl_xor_sync(0xffffffffu, qsum, o);
    if (lane == 0) qw[tid >> 5] = qsum;
    __syncthreads();
    if (tid < 16) {
        float v = qw[tid];
        v += __shfl_xor_sync(0x0000ffffu, v, 8);
        v += __shfl_xor_sync(0x0000ffffu, v, 4);
        v += __shfl_xor_sync(0x0000ffffu, v, 2);
        v += __shfl_xor_sync(0x0000ffffu, v, 1);
        if (tid == 0) g_q_part[by * gridDim.x + bx] = v;
    }

    __shared__ int isLast;
    if (tid == 0) {
        __threadfence();
        isLast = (atomicAdd(&g_done_main, 1) == MAINB - 1);
    }
    __syncthreads();
    if (isLast) {
        __threadfence();
        float s = g_q_part[tid];          // MAINB == NT2 == 512
#pragma unroll
        for (int o = 16; o > 0; o >>= 1) s += __shfl_xor_sync(0xffffffffu, s, o);
        if (lane == 0) qw[tid >> 5] = s;
        __syncthreads();
        if (tid < 16) {
            float v = qw[tid];
            v += __shfl_xor_sync(0x0000ffffu, v, 8);
            v += __shfl_xor_sync(0x0000ffffu, v, 4);
            v += __shfl_xor_sync(0x0000ffffu, v, 2);
            v += __shfl_xor_sync(0x0000ffffu, v, 1);
            if (tid == 0) {
                if (q_out) q_out[0] = v / (float)NPIX;
                g_done_main = 0;
            }
        }
    }
}

// ---------------- launch ----------------
extern "C" void kernel_launch(void* const* d_in, const int* in_sizes, int n_in,
                              void* d_out, int out_size) {
    const float* a = (const float*)d_in[0];
    const float* b = (const float*)d_in[1];
    const float* img;
    const float* bunch;
    if (in_sizes[0] > in_sizes[1]) { bunch = a; img = b; }
    else                           { img = a;  bunch = b; }

    float* out = (float*)d_out;
    float* qdst = nullptr;
    float* patch = nullptr;
    if (out_size >= NPIX + 1)      { qdst = out; patch = out + 1; }
    else if (out_size == NPIX)     { patch = out; }
    else                           { qdst = out; }

    // host-side double-precision gaussian window
    GW gwp;
    {
        double t[WS], s = 0.0;
        double sg = (double)WS / 6.0;
        for (int i = 0; i < WS; i++) {
            double d = (double)(i - RAD);
            t[i] = exp(-(d * d) / (2.0 * sg * sg));
            s += t[i];
        }
        for (int i = 0; i < WS; i++) gwp.w[i] = (float)(t[i] / s);
    }

    static bool attr_set = false;
    if (!attr_set) {
        cudaFuncSetAttribute(mef_main_k, cudaFuncAttributeMaxDynamicSharedMemorySize, SMEM_TOTAL);
        attr_set = true;
    }

    lY_prepass<<<PREB, NT>>>(bunch, gwp);
    mef_main_k<<<dim3(WW / TW, HH / TH), NT2, SMEM_TOTAL>>>(img, bunch, patch, qdst, gwp);
}

// round 8
// speedup vs baseline: 1.7561x; 1.1729x over previous
#include <cuda_runtime.h>
#include <cuda_fp16.h>
#include <math.h>

// ---------------- problem constants ----------------
#define HH      1024
#define WW      1024
#define NPIX    (HH * WW)
#define KK      8
#define WS      11
#define RAD     5

// ---------------- main tiling: 64 x 32 tiles, 512 threads ----------------
#define TW       64
#define TH       32
#define HTW      74            // TW + 2*RAD
#define HTH      42            // TH + 2*RAD
#define HT       (HTW * HTH)   // 3108
#define NT2      512
#define NLOAD    7             // ceil(HT / NT2)
#define VBW      75            // vb row stride (float2 / float units)
#define MAINB    512           // (1024/64)*(1024/32)

// smem layout (bytes), 16B-aligned
#define OFF_F01   0                       // float2[HT]      24864
#define OFF_F2    24864                   // float [HT]      12432
#define OFF_VB01  37296                   // float2[32*75]   19200
#define OFF_VB2   56496                   // float [32*75]    9600
#define SMEM_TOTAL 66096

struct GW { float w[WS]; };

// ---------------- scratch (static device globals; no allocation) ----------------
__device__ uint2 g_muY2[KK * NPIX / 4];   // per-pixel muYs (shifted) as 4 halfs, tile-private layout (16MB)
__device__ uint2 g_cs2[NPIX / 4];         // per-pixel cs_map as 4 halfs (2MB)
__device__ uint2 g_mx2[NPIX / 4];         // per-pixel muXs (shifted) as 4 halfs (2MB)
__device__ float g_lY_part[KK * MAINB];
__device__ float g_lG[KK];
__device__ float g_q_part[MAINB];
__device__ int   g_done1 = 0;
__device__ int   g_done2 = 0;

// ======================= separable blur helpers =======================
// Vertical: 6 consecutive output rows per task, 16 taps -> 2.67 loads/output.
__device__ __forceinline__ void vpass6(const float2* __restrict__ f01,
                                       const float* __restrict__ f2,
                                       float2* __restrict__ vb01,
                                       float* __restrict__ vb2,
                                       const float* gw, int tid) {
    if (tid < 444) {
        int g = tid / HTW, c = tid - g * HTW;
        int r0 = g * 6;
        float ax[6], ay[6], az[6];
#pragma unroll
        for (int i = 0; i < 6; i++) { ax[i] = 0.f; ay[i] = 0.f; az[i] = 0.f; }
        const float2* p01 = f01 + r0 * HTW + c;
        const float*  p2  = f2  + r0 * HTW + c;
#pragma unroll
        for (int j = 0; j < 16; j++) {
            if (r0 + j < HTH) {
                float2 v = p01[j * HTW];
                float  z = p2[j * HTW];
#pragma unroll
                for (int i = 0; i < 6; i++) {
                    if (i <= j && j - i <= 10) {
                        float gg = gw[j - i];
                        ax[i] += gg * v.x; ay[i] += gg * v.y; az[i] += gg * z;
                    }
                }
            }
        }
#pragma unroll
        for (int i = 0; i < 6; i++) {
            int r = r0 + i;
            if (r < TH) {
                vb01[r * VBW + c] = make_float2(ax[i], ay[i]);
                vb2[r * VBW + c] = az[i];
            }
        }
    }
}

// Horizontal: lane = row (conflict-free strides), 4 cols/thread.
__device__ __forceinline__ void hpass(const float2* __restrict__ vb01,
                                      const float* __restrict__ vb2,
                                      const float* gw, int row, int x0, float3* out) {
    float ax[4], ay[4], az[4];
#pragma unroll
    for (int i = 0; i < 4; i++) { ax[i] = 0.f; ay[i] = 0.f; az[i] = 0.f; }
    const float2* p01 = vb01 + row * VBW + x0;
    const float*  p2  = vb2  + row * VBW + x0;
#pragma unroll
    for (int j = 0; j < 14; j++) {
        float2 v = p01[j];
        float  z = p2[j];
#pragma unroll
        for (int i = 0; i < 4; i++) {
            if (i <= j && j - i <= 10) {
                float gg = gw[j - i];
                ax[i] += gg * v.x; ay[i] += gg * v.y; az[i] += gg * z;
            }
        }
    }
#pragma unroll
    for (int i = 0; i < 4; i++) out[i] = make_float3(ax[i], ay[i], az[i]);
}

// Pack-write: load bunch k tile (shifted), build (s, s², s·o') fields.
__device__ __forceinline__ void pack_write(const float* __restrict__ bb,
                                           const int* goff, const __half2* h01,
                                           const __half2* h2p,
                                           float2* __restrict__ s_f01,
                                           float* __restrict__ s_f2, int tid) {
#pragma unroll
    for (int i = 0; i < NLOAD; i++) {
        int e = tid + i * NT2;
        if (e < HT) {
            int o = goff[i];
            float v0 = -0.5f, v1 = -0.5f, v2 = -0.5f;
            if (o >= 0) {
                v0 = bb[o] - 0.5f; v1 = bb[NPIX + o] - 0.5f; v2 = bb[2 * NPIX + o] - 0.5f;
            }
            float2 o01 = __half22float2(h01[i]);
            float  o2  = __half2float((i & 1) ? __high2half(h2p[i >> 1])
                                              : __low2half(h2p[i >> 1]));
            s_f01[e] = make_float2((v0 + v1 + v2) * (1.f / 3.f),
                                   (v0 * v0 + v1 * v1 + v2 * v2) * (1.f / 3.f));
            s_f2[e]  = (v0 * o01.x + v1 * o01.y + v2 * o2) * (1.f / 3.f);
        }
    }
}

__device__ __forceinline__ uint2 pack4h(float a, float b, float c, float d) {
    __half2 p0 = __floats2half2_rn(a, b);
    __half2 p1 = __floats2half2_rn(c, d);
    uint2 u;
    u.x = *(const unsigned int*)&p0;
    u.y = *(const unsigned int*)&p1;
    return u;
}

// ======================= k1: stats pass =======================
// Shifted domain v' = v - 0.5 (exact; reference zero-pads raw => padded v' = -0.5).
__global__ __launch_bounds__(NT2, 2) void mef_stats_k(
    const float* __restrict__ img,
    const float* __restrict__ bunch,
    float* __restrict__ patch_out,
    GW gwp)
{
    extern __shared__ char sm[];
    float2* s_f01  = (float2*)(sm + OFF_F01);
    float*  s_f2   = (float*)(sm + OFF_F2);
    float2* s_vb01 = (float2*)(sm + OFF_VB01);
    float*  s_vb2  = (float*)(sm + OFF_VB2);
    __shared__ float s_ly[16 * KK];     // per-warp per-k lY partials
    __shared__ float qw[16];
    const float* gw = gwp.w;

    int tid = threadIdx.x;
    int lane = tid & 31;
    int wid = tid >> 5;
    int row = tid & 31;          // hpass: output row
    int x0c = (tid >> 5) * 4;    // hpass: 4 consecutive output cols
    int bx = blockIdx.x, by = blockIdx.y;
    int T  = by * gridDim.x + bx;    // tile id 0..511
    int gx0 = bx * TW - RAD, gy0 = by * TH - RAD;

    // per-thread halo state: global offsets + output-image channels (half regs)
    int goff[NLOAD];
    __half2 h01[NLOAD];          // (o0', o1')
    __half2 h2p[4];              // o2' packed pairs
#pragma unroll
    for (int i = 0; i < 4; i++) h2p[i] = __halves2half2(__float2half(0.f), __float2half(0.f));

#pragma unroll
    for (int i = 0; i < NLOAD; i++) {
        int e = tid + i * NT2;
        float o0 = -0.5f, o1 = -0.5f, o2 = -0.5f;
        int o = -2;
        if (e < HT) {
            int hy = e / HTW, hx = e - hy * HTW;
            int gy = gy0 + hy, gx = gx0 + hx;
            o = (((unsigned)gy < HH) && ((unsigned)gx < WW)) ? gy * WW + gx : -1;
            if (o >= 0) {
                o0 = img[o] - 0.5f; o1 = img[NPIX + o] - 0.5f; o2 = img[2 * NPIX + o] - 0.5f;
            }
            s_f01[e] = make_float2((o0 + o1 + o2) * (1.f / 3.f),
                                   (o0 * o0 + o1 * o1 + o2 * o2) * (1.f / 3.f));
            s_f2[e] = 0.f;
        }
        goff[i] = o;
        h01[i] = __floats2half2_rn(o0, o1);
        __half h2v = __float2half_rn(o2);
        if (i & 1) h2p[i >> 1] = __halves2half2(__low2half(h2p[i >> 1]), h2v);
        else       h2p[i >> 1] = __halves2half2(h2v, __high2half(h2p[i >> 1]));
    }
    __syncthreads();

    vpass6(s_f01, s_f2, s_vb01, s_vb2, gw, tid);
    __syncthreads();                 // vb ready; pack free
    float3 xo[4];
    hpass(s_vb01, s_vb2, gw, row, x0c, xo);
    float muXs[4], sX2[4];
#pragma unroll
    for (int i = 0; i < 4; i++) { muXs[i] = xo[i].x; sX2[i] = xo[i].y - muXs[i] * muXs[i]; }

    // write pack for k=0 while other warps still in hpass (same barrier interval)
    pack_write(bunch, goff, h01, h2p, s_f01, s_f2, tid);
    __syncthreads();                 // pack(0) ready; vb consumed

    float best[4], bestXY[4];
    int pidx[4];
#pragma unroll
    for (int i = 0; i < 4; i++) { best[i] = -1e30f; bestXY[i] = 0.f; pidx[i] = 0; }

    for (int k = 0; k < KK; k++) {
        vpass6(s_f01, s_f2, s_vb01, s_vb2, gw, tid);
        __syncthreads();             // vb ready; pack free
        float3 yo[4];
        hpass(s_vb01, s_vb2, gw, row, x0c, yo);

#pragma unroll
        for (int i = 0; i < 4; i++) {
            float muYs = yo[i].x;
            float sY2 = yo[i].y - muYs * muYs;
            float sXY = yo[i].z - muXs[i] * muYs;
            if (sY2 > best[i]) { best[i] = sY2; bestXY[i] = sXY; pidx[i] = k; }
        }
        // store muYs for blend pass (half, tile-private coalesced layout)
        g_muY2[(size_t)(T * KK + k) * NT2 + tid] =
            pack4h(yo[0].x, yo[1].x, yo[2].x, yo[3].x);
        // per-warp lY partial (exact: tiles partition image)
        float lsum = yo[0].x + yo[1].x + yo[2].x + yo[3].x;
#pragma unroll
        for (int o = 16; o > 0; o >>= 1) lsum += __shfl_xor_sync(0xffffffffu, lsum, o);
        if (lane == 0) s_ly[wid * KK + k] = lsum;

        // prefetch + pack next exposure, overlapping hpass/stat issue stream
        if (k < KK - 1)
            pack_write(bunch + (size_t)(3 * (k + 1)) * NPIX, goff, h01, h2p,
                       s_f01, s_f2, tid);
        __syncthreads();             // pack(k+1) ready; vb consumed; s_ly visible
    }

    // ---- epilogue ----
    // lY partials: fold 16 warps per k (8 threads, deterministic serial order)
    if (tid < KK) {
        float v = 0.f;
#pragma unroll
        for (int w = 0; w < 16; w++) v += s_ly[w * KK + tid];
        g_lY_part[tid * MAINB + T] = v;
    }

    // cs + muXs (half) and patch staging
    float* sidx = (float*)s_vb01;   // staging: 32 x 64 floats
    float csv[4];
#pragma unroll
    for (int i = 0; i < 4; i++) {
        csv[i] = (2.f * bestXY[i] + 9e-4f) /
                 fmaxf(sX2[i] + best[i] + 9e-4f, 1e-6f);   // C2 = 0.03^2
        sidx[row * 64 + x0c + i] = (float)pidx[i];
    }
    g_cs2[(size_t)T * NT2 + tid] = pack4h(csv[0], csv[1], csv[2], csv[3]);
    g_mx2[(size_t)T * NT2 + tid] = pack4h(muXs[0], muXs[1], muXs[2], muXs[3]);

    __syncthreads();
    if (patch_out) {
        // scalar stores: patch_out base is only 4B-aligned (out + 1).
        int px = tid * 4;
        int rr = px >> 6, cc = px & 63;
        float* dst = &patch_out[(by * TH + rr) * WW + bx * TW + cc];
        const float* src = &sidx[px];
        dst[0] = src[0]; dst[1] = src[1]; dst[2] = src[2]; dst[3] = src[3];
    }

    // ---- last block: fold lY partials -> lG ----
    __shared__ int isLast;
    if (tid == 0) {
        __threadfence();
        isLast = (atomicAdd(&g_done1, 1) == MAINB - 1);
    }
    __syncthreads();
    if (isLast) {
        __threadfence();
        for (int k = 0; k < KK; k++) {
            float s = g_lY_part[k * MAINB + tid];     // MAINB == NT2 == 512
#pragma unroll
            for (int o = 16; o > 0; o >>= 1) s += __shfl_xor_sync(0xffffffffu, s, o);
            if (lane == 0) qw[wid] = s;
            __syncthreads();
            if (tid < 16) {
                float v = qw[tid];
                v += __shfl_xor_sync(0x0000ffffu, v, 8);
                v += __shfl_xor_sync(0x0000ffffu, v, 4);
                v += __shfl_xor_sync(0x0000ffffu, v, 2);
                v += __shfl_xor_sync(0x0000ffffu, v, 1);
                if (tid == 0) {
                    double d = (double)v / (double)NPIX;   // = mean(muYs) = lY - 0.5
                    g_lG[k] = (float)exp(-(d * d) / 0.08); // DENOM_G = 2*0.2^2
                }
            }
            __syncthreads();
        }
        if (tid == 0) g_done1 = 0;   // self-reset for next graph replay
    }
}

// ======================= k2: luminance blend + q =======================
__global__ __launch_bounds__(NT2) void mef_blend_k(float* __restrict__ q_out) {
    __shared__ float s_lG[KK];
    __shared__ float qw[16];
    int tid = threadIdx.x;
    int lane = tid & 31, wid = tid >> 5;
    int T = blockIdx.x;

    if (tid < KK) s_lG[tid] = g_lG[tid];
    __syncthreads();

    float num[4], den[4];
#pragma unroll
    for (int i = 0; i < 4; i++) { num[i] = 0.f; den[i] = 0.f; }

#pragma unroll
    for (int k = 0; k < KK; k++) {
        uint2 u = g_muY2[(size_t)(T * KK + k) * NT2 + tid];
        __half2 pa = *(const __half2*)&u.x;
        __half2 pb = *(const __half2*)&u.y;
        float2 f0 = __half22float2(pa);
        float2 f1 = __half22float2(pb);
        float m[4] = {f0.x, f0.y, f1.x, f1.y};
        float lGk = s_lG[k];
#pragma unroll
        for (int i = 0; i < 4; i++) {
            float wgt = lGk * __expf(-(m[i] * m[i]) * (1.f / 0.08f));   // DENOM_L
            num[i] += wgt * (m[i] + 0.5f);
            den[i] += wgt;
        }
    }

    uint2 cu = g_cs2[(size_t)T * NT2 + tid];
    uint2 mu = g_mx2[(size_t)T * NT2 + tid];
    float2 c0 = __half22float2(*(const __half2*)&cu.x);
    float2 c1 = __half22float2(*(const __half2*)&cu.y);
    float2 x0 = __half22float2(*(const __half2*)&mu.x);
    float2 x1 = __half22float2(*(const __half2*)&mu.y);
    float cs[4] = {c0.x, c0.y, c1.x, c1.y};
    float mx[4] = {x0.x, x0.y, x1.x, x1.y};

    float qsum = 0.f;
#pragma unroll
    for (int i = 0; i < 4; i++) {
        float muX  = mx[i] + 0.5f;
        float muYb = num[i] / den[i];
        float l = (2.f * muX * muYb + 1e-4f) /
                  fmaxf(muX * muX + muYb * muYb + 1e-4f, 1e-6f);   // C1 = 0.01^2
        qsum += l * cs[i];
    }

#pragma unroll
    for (int o = 16; o > 0; o >>= 1) qsum += __shfl_xor_sync(0xffffffffu, qsum, o);
    if (lane == 0) qw[wid] = qsum;
    __syncthreads();
    if (tid < 16) {
        float v = qw[tid];
        v += __shfl_xor_sync(0x0000ffffu, v, 8);
        v += __shfl_xor_sync(0x0000ffffu, v, 4);
        v += __shfl_xor_sync(0x0000ffffu, v, 2);
        v += __shfl_xor_sync(0x0000ffffu, v, 1);
        if (tid == 0) g_q_part[T] = v;
    }

    __shared__ int isLast;
    if (tid == 0) {
        __threadfence();
        isLast = (atomicAdd(&g_done2, 1) == MAINB - 1);
    }
    __syncthreads();
    if (isLast) {
        __threadfence();
        float s = g_q_part[tid];          // MAINB == NT2 == 512
#pragma unroll
        for (int o = 16; o > 0; o >>= 1) s += __shfl_xor_sync(0xffffffffu, s, o);
        if (lane == 0) qw[wid] = s;
        __syncthreads();
        if (tid < 16) {
            float v = qw[tid];
            v += __shfl_xor_sync(0x0000ffffu, v, 8);
            v += __shfl_xor_sync(0x0000ffffu, v, 4);
            v += __shfl_xor_sync(0x0000ffffu, v, 2);
            v += __shfl_xor_sync(0x0000ffffu, v, 1);
            if (tid == 0) {
                if (q_out) q_out[0] = v / (float)NPIX;
                g_done2 = 0;
            }
        }
    }
}

// ---------------- launch ----------------
extern "C" void kernel_launch(void* const* d_in, const int* in_sizes, int n_in,
                              void* d_out, int out_size) {
    const float* a = (const float*)d_in[0];
    const float* b = (const float*)d_in[1];
    const float* img;
    const float* bunch;
    if (in_sizes[0] > in_sizes[1]) { bunch = a; img = b; }
    else                           { img = a;  bunch = b; }

    float* out = (float*)d_out;
    float* qdst = nullptr;
    float* patch = nullptr;
    if (out_size >= NPIX + 1)      { qdst = out; patch = out + 1; }
    else if (out_size == NPIX)     { patch = out; }
    else                           { qdst = out; }

    // host-side double-precision gaussian window
    GW gwp;
    {
        double t[WS], s = 0.0;
        double sg = (double)WS / 6.0;
        for (int i = 0; i < WS; i++) {
            double d = (double)(i - RAD);
            t[i] = exp(-(d * d) / (2.0 * sg * sg));
            s += t[i];
        }
        for (int i = 0; i < WS; i++) gwp.w[i] = (float)(t[i] / s);
    }

    static bool attr_set = false;
    if (!attr_set) {
        cudaFuncSetAttribute(mef_stats_k, cudaFuncAttributeMaxDynamicSharedMemorySize, SMEM_TOTAL);
        attr_set = true;
    }

    mef_stats_k<<<dim3(WW / TW, HH / TH), NT2, SMEM_TOTAL>>>(img, bunch, patch, gwp);
    mef_blend_k<<<MAINB, NT2>>>(qdst);
}